// round 1
// baseline (speedup 1.0000x reference)
#include <cuda_runtime.h>

// ---------------------------------------------------------------------------
// Problem constants
// ---------------------------------------------------------------------------
#define N0 262144
#define N1 32768
#define N2 4096
#define K3 27
#define K2 8
#define C_IN 3
#define C0 24
#define C1 48
#define C2 96
#define BN_EPS 1e-5f

typedef unsigned long long u64;

__device__ __forceinline__ u64 pack2(float v) {
    u64 r;
    asm("mov.b64 %0, {%1, %1};" : "=l"(r) : "f"(v));
    return r;
}
__device__ __forceinline__ void fma2(u64& d, u64 a, u64 b) {
    asm("fma.rn.f32x2 %0, %1, %2, %0;" : "+l"(d) : "l"(a), "l"(b));
}
__device__ __forceinline__ void unpack2(u64 v, float& lo, float& hi) {
    asm("mov.b64 {%0, %1}, %2;" : "=f"(lo), "=f"(hi) : "l"(v));
}

// ---------------------------------------------------------------------------
// Scratch (static device arrays; no allocation allowed)
// ---------------------------------------------------------------------------
__device__ float g_y0[N0 * C0];     // stage A output  (25.2 MB)
__device__ float g_y1[N1 * C1];     // stage B output
__device__ float g_y2[N1 * C1];     // stage C output
__device__ float g_y3[N2 * C2];     // stage D output
__device__ float g_stats[5 * 192];  // per-stage [sum | sumsq], 96 max channels
__device__ float g_sb[5 * 192];     // per-stage [scale | shift]

// ---------------------------------------------------------------------------
// init: zero stats + accumulated buffers (+ d_out, accumulated by stage E)
// ---------------------------------------------------------------------------
__global__ void init_kernel(float* __restrict__ out) {
    int t = blockIdx.x * blockDim.x + threadIdx.x;
    int stride = gridDim.x * blockDim.x;
    for (int i = t; i < 5 * 192; i += stride) g_stats[i] = 0.f;
    for (int i = t; i < N1 * C1; i += stride) { g_y1[i] = 0.f; g_y2[i] = 0.f; }
    for (int i = t; i < N2 * C2; i += stride) { g_y3[i] = 0.f; out[i] = 0.f; }
}

// ---------------------------------------------------------------------------
// Fused gather + (optional input BN/ReLU) + conv-contract kernel.
//   y[n, dbase+d] (+)= sum_{k in block's k-range} sum_c xn(idx[n,k], c) * W[k,c,dbase+d]
//   xn(r,c) = NORM_IN ? relu(x[r,c]*s[c]+t[c]) : x[r,c]
// One thread per output row (256 rows per block). DCHUNK outputs per thread,
// accumulated as packed f32x2. W slice staged in shared, broadcast LDS.
// ---------------------------------------------------------------------------
template <int K, int KPB, int CIN, int COUT, int DCHUNK,
          bool NORM_IN, bool PRELOAD, bool ACCUM>
__global__ void __launch_bounds__(256) conv_kernel(
    const float* __restrict__ x, const int* __restrict__ neigh,
    const float* __restrict__ W, const float* __restrict__ sb,
    float* __restrict__ y, int N)
{
    constexpr int ROWS = 256;
    constexpr int CH = (CIN % 24 == 0) ? 24 : CIN;  // c half-width kept in regs
    constexpr int NH = CIN / CH;
    constexpr int WBUF = (PRELOAD ? KPB : 1) * CIN * DCHUNK;

    __shared__ int sh_idx[ROWS * KPB];
    __shared__ __align__(16) float sh_w[WBUF];
    __shared__ float sh_s[CIN];
    __shared__ float sh_t[CIN];

    const int tid = threadIdx.x;
    const int n0 = blockIdx.x * ROWS;
    const int dbase = blockIdx.y * DCHUNK;
    const int k0 = blockIdx.z * KPB;
    const int n = n0 + tid;

    // stage neighbor indices for this block's rows / k-range (coalesced-ish)
    #pragma unroll 1
    for (int i = tid; i < ROWS * KPB; i += ROWS) {
        int r = i / KPB, kk = i % KPB;
        sh_idx[i] = neigh[(size_t)(n0 + r) * K + (k0 + kk)];
    }
    if (NORM_IN) {
        for (int i = tid; i < CIN; i += ROWS) {
            sh_s[i] = sb[i];
            sh_t[i] = sb[CIN + i];
        }
    }
    if (PRELOAD) {
        #pragma unroll 1
        for (int i = tid; i < WBUF; i += ROWS) {
            int kk = i / (CIN * DCHUNK);
            int rem = i % (CIN * DCHUNK);
            int c = rem / DCHUNK, d = rem % DCHUNK;
            sh_w[i] = W[((size_t)(k0 + kk) * CIN + c) * COUT + dbase + d];
        }
    }
    __syncthreads();

    u64 acc[DCHUNK / 2];
    #pragma unroll
    for (int j = 0; j < DCHUNK / 2; ++j) acc[j] = 0ull;

    #pragma unroll 1
    for (int kk = 0; kk < KPB; ++kk) {
        if (!PRELOAD) {
            __syncthreads();
            #pragma unroll 1
            for (int i = tid; i < CIN * DCHUNK; i += ROWS) {
                int c = i / DCHUNK, d = i % DCHUNK;
                sh_w[i] = W[((size_t)(k0 + kk) * CIN + c) * COUT + dbase + d];
            }
            __syncthreads();
        }
        const float* wk = PRELOAD ? (sh_w + kk * CIN * DCHUNK) : sh_w;
        const int idx = sh_idx[tid * KPB + kk];
        const float* xrow = x + (size_t)idx * CIN;

        #pragma unroll
        for (int h = 0; h < NH; ++h) {
            float xh[CH];
            if (CH % 4 == 0) {
                #pragma unroll
                for (int j4 = 0; j4 < CH / 4; ++j4) {
                    float4 v = *(const float4*)(xrow + h * CH + j4 * 4);
                    xh[4 * j4 + 0] = v.x;
                    xh[4 * j4 + 1] = v.y;
                    xh[4 * j4 + 2] = v.z;
                    xh[4 * j4 + 3] = v.w;
                }
            } else {
                #pragma unroll
                for (int j = 0; j < CH; ++j) xh[j] = xrow[h * CH + j];
            }
            if (NORM_IN) {
                #pragma unroll
                for (int j = 0; j < CH; ++j)
                    xh[j] = fmaxf(xh[j] * sh_s[h * CH + j] + sh_t[h * CH + j], 0.f);
            }
            #pragma unroll
            for (int c = 0; c < CH; ++c) {
                u64 xv2 = pack2(xh[c]);
                const u64* wrow = (const u64*)(wk + (h * CH + c) * DCHUNK);
                #pragma unroll
                for (int j = 0; j < DCHUNK / 2; ++j) fma2(acc[j], xv2, wrow[j]);
            }
        }
    }

    float* yrow = y + (size_t)n * COUT + dbase;
    if (ACCUM) {
        #pragma unroll
        for (int j = 0; j < DCHUNK / 2; ++j) {
            float lo, hi;
            unpack2(acc[j], lo, hi);
            atomicAdd(yrow + 2 * j, lo);
            atomicAdd(yrow + 2 * j + 1, hi);
        }
    } else {
        #pragma unroll
        for (int j = 0; j < DCHUNK / 4; ++j) {
            float4 v;
            unpack2(acc[2 * j],     v.x, v.y);
            unpack2(acc[2 * j + 1], v.z, v.w);
            *(float4*)(yrow + 4 * j) = v;
        }
    }
}

// ---------------------------------------------------------------------------
// Per-channel sum / sumsq reduction. blockDim = (C, 8).
// ---------------------------------------------------------------------------
template <int C>
__global__ void stats_kernel(const float* __restrict__ y, int N,
                             float* __restrict__ stats)
{
    const int c = threadIdx.x;
    const int ty = threadIdx.y;
    float s = 0.f, q = 0.f;
    for (int r = blockIdx.x * blockDim.y + ty; r < N; r += gridDim.x * blockDim.y) {
        float v = y[(size_t)r * C + c];
        s += v;
        q += v * v;
    }
    __shared__ float sh[2][8][C];
    sh[0][ty][c] = s;
    sh[1][ty][c] = q;
    __syncthreads();
    if (ty == 0) {
        #pragma unroll
        for (int j = 1; j < 8; ++j) { s += sh[0][j][c]; q += sh[1][j][c]; }
        atomicAdd(&stats[c], s);
        atomicAdd(&stats[C + c], q);
    }
}

// ---------------------------------------------------------------------------
// BN finalize: scale/shift from batch stats. One block, C threads.
// ---------------------------------------------------------------------------
template <int C>
__global__ void finalize_kernel(const float* __restrict__ stats,
                                const float* __restrict__ g,
                                const float* __restrict__ b,
                                float* __restrict__ sb, float invN)
{
    int c = threadIdx.x;
    float mu = stats[c] * invN;
    float var = fmaxf(stats[C + c] * invN - mu * mu, 0.f);
    float s = g[c] * rsqrtf(var + BN_EPS);
    sb[c] = s;
    sb[C + c] = b[c] - mu * s;
}

// ---------------------------------------------------------------------------
// Final normalize + ReLU (in place on d_out)
// ---------------------------------------------------------------------------
__global__ void norm_out_kernel(float* __restrict__ out, const float* __restrict__ sb) {
    int i = blockIdx.x * blockDim.x + threadIdx.x;
    if (i < N2 * C2) {
        int c = i % C2;
        out[i] = fmaxf(out[i] * sb[c] + sb[C2 + c], 0.f);
    }
}

// ---------------------------------------------------------------------------
// Host launcher (graph-capturable: kernel launches only)
// ---------------------------------------------------------------------------
extern "C" void kernel_launch(void* const* d_in, const int* in_sizes, int n_in,
                              void* d_out, int out_size)
{
    const float* data   = (const float*)d_in[0];
    const int*   neigh0 = (const int*)  d_in[1];
    const int*   child0 = (const int*)  d_in[2];
    const int*   neigh1 = (const int*)  d_in[3];
    const int*   child1 = (const int*)  d_in[4];
    const int*   neigh2 = (const int*)  d_in[5];
    const float* w0  = (const float*)d_in[6];
    const float* g0  = (const float*)d_in[7];
    const float* b0  = (const float*)d_in[8];
    const float* wd0 = (const float*)d_in[9];
    const float* gd0 = (const float*)d_in[10];
    const float* bd0 = (const float*)d_in[11];
    const float* w1  = (const float*)d_in[12];
    const float* g1  = (const float*)d_in[13];
    const float* b1  = (const float*)d_in[14];
    const float* wd1 = (const float*)d_in[15];
    const float* gd1 = (const float*)d_in[16];
    const float* bd1 = (const float*)d_in[17];
    const float* wp  = (const float*)d_in[18];
    const float* gp  = (const float*)d_in[19];
    const float* bp  = (const float*)d_in[20];
    float* out = (float*)d_out;

    float *y0p, *y1p, *y2p, *y3p, *stp, *sbp;
    cudaGetSymbolAddress((void**)&y0p, g_y0);
    cudaGetSymbolAddress((void**)&y1p, g_y1);
    cudaGetSymbolAddress((void**)&y2p, g_y2);
    cudaGetSymbolAddress((void**)&y3p, g_y3);
    cudaGetSymbolAddress((void**)&stp, g_stats);
    cudaGetSymbolAddress((void**)&sbp, g_sb);

    init_kernel<<<512, 256>>>(out);

    // Stage A: data[N0,3] -> y0[N0,24]   (K=27, preload full W, direct store)
    conv_kernel<K3, K3, C_IN, C0, C0, false, true, false>
        <<<dim3(N0 / 256, 1, 1), 256>>>(data, neigh0, w0, nullptr, y0p, N0);
    stats_kernel<C0><<<256, dim3(C0, 8)>>>(y0p, N0, stp + 0);
    finalize_kernel<C0><<<1, C0>>>(stp + 0, g0, b0, sbp + 0, 1.f / N0);

    // Stage B: y0 -> y1[N1,48]   (K=8, split k into 2 groups of 4, atomic accum)
    conv_kernel<K2, 4, C0, C1, C1, true, true, true>
        <<<dim3(N1 / 256, 1, 2), 256>>>(y0p, child0, wd0, sbp + 0, y1p, N1);
    stats_kernel<C1><<<256, dim3(C1, 8)>>>(y1p, N1, stp + 192);
    finalize_kernel<C1><<<1, C1>>>(stp + 192, gd0, bd0, sbp + 192, 1.f / N1);

    // Stage C: y1 -> y2[N1,48]   (K=27, split k into 3 groups of 9, per-k W staging)
    conv_kernel<K3, 9, C1, C1, C1, true, false, true>
        <<<dim3(N1 / 256, 1, 3), 256>>>(y1p, neigh1, w1, sbp + 192, y2p, N1);
    stats_kernel<C1><<<256, dim3(C1, 8)>>>(y2p, N1, stp + 384);
    finalize_kernel<C1><<<1, C1>>>(stp + 384, g1, b1, sbp + 384, 1.f / N1);

    // Stage D: y2 -> y3[N2,96]   (K=8, 2 d-chunks, k split into 8 singles)
    conv_kernel<K2, 1, C1, C2, 48, true, true, true>
        <<<dim3(N2 / 256, 2, 8), 256>>>(y2p, child1, wd1, sbp + 384, y3p, N2);
    stats_kernel<C2><<<256, dim3(C2, 8)>>>(y3p, N2, stp + 576);
    finalize_kernel<C2><<<1, C2>>>(stp + 576, gd1, bd1, sbp + 576, 1.f / N2);

    // Stage E: y3 -> d_out[N2,96] raw conv  (K=27, 2 d-chunks, k split 9x3)
    conv_kernel<K3, 3, C2, C2, 48, true, false, true>
        <<<dim3(N2 / 256, 2, 9), 256>>>(y3p, neigh2, wp, sbp + 576, out, N2);
    stats_kernel<C2><<<256, dim3(C2, 8)>>>(out, N2, stp + 768);
    finalize_kernel<C2><<<1, C2>>>(stp + 768, gp, bp, sbp + 768, 1.f / N2);

    // Final BN + ReLU in place on d_out
    norm_out_kernel<<<(N2 * C2 + 255) / 256, 256>>>(out, sbp + 768);
}

// round 2
// speedup vs baseline: 1.0014x; 1.0014x over previous
#include <cuda_runtime.h>

// ---------------------------------------------------------------------------
// Problem constants
// ---------------------------------------------------------------------------
#define N0 262144
#define N1 32768
#define N2 4096
#define K3 27
#define K2 8
#define C_IN 3
#define C0 24
#define C1 48
#define C2 96
#define BN_EPS 1e-5f

typedef unsigned long long u64;

__device__ __forceinline__ u64 pack2(float v) {
    u64 r;
    asm("mov.b64 %0, {%1, %1};" : "=l"(r) : "f"(v));
    return r;
}
__device__ __forceinline__ void fma2(u64& d, u64 a, u64 b) {
    asm("fma.rn.f32x2 %0, %1, %2, %0;" : "+l"(d) : "l"(a), "l"(b));
}
__device__ __forceinline__ void unpack2(u64 v, float& lo, float& hi) {
    asm("mov.b64 {%0, %1}, %2;" : "=f"(lo), "=f"(hi) : "l"(v));
}

// ---------------------------------------------------------------------------
// Scratch (static device arrays; no allocation allowed)
// ---------------------------------------------------------------------------
__device__ float g_y0[N0 * C0];     // stage A output  (25.2 MB)
__device__ float g_y1[N1 * C1];     // stage B output
__device__ float g_y2[N1 * C1];     // stage C output
__device__ float g_y3[N2 * C2];     // stage D output
__device__ float g_stats[5 * 192];  // per-stage [sum | sumsq], 96 max channels
__device__ float g_sb[5 * 192];     // per-stage [scale | shift]

// ---------------------------------------------------------------------------
// init: zero stats + accumulated buffers (+ d_out, accumulated by stage E)
// ---------------------------------------------------------------------------
__global__ void init_kernel(float* __restrict__ out) {
    int t = blockIdx.x * blockDim.x + threadIdx.x;
    int stride = gridDim.x * blockDim.x;
    for (int i = t; i < 5 * 192; i += stride) g_stats[i] = 0.f;
    for (int i = t; i < N1 * C1; i += stride) { g_y1[i] = 0.f; g_y2[i] = 0.f; }
    for (int i = t; i < N2 * C2; i += stride) { g_y3[i] = 0.f; out[i] = 0.f; }
}

// ---------------------------------------------------------------------------
// Fused gather + (optional input BN/ReLU) + conv-contract kernel.
//   y[n, dbase+d] (+)= sum_{k in block's k-range} sum_c xn(idx[n,k], c) * W[k,c,dbase+d]
//   xn(r,c) = NORM_IN ? relu(x[r,c]*s[c]+t[c]) : x[r,c]
// One thread per output row (256 rows per block). DCHUNK outputs per thread,
// accumulated as packed f32x2. W slice staged in shared, broadcast LDS.
// ---------------------------------------------------------------------------
template <int K, int KPB, int CIN, int COUT, int DCHUNK,
          bool NORM_IN, bool PRELOAD, bool ACCUM>
__global__ void __launch_bounds__(256) conv_kernel(
    const float* __restrict__ x, const int* __restrict__ neigh,
    const float* __restrict__ W, const float* __restrict__ sb,
    float* __restrict__ y, int N)
{
    constexpr int ROWS = 256;
    constexpr int CH = (CIN % 24 == 0) ? 24 : CIN;  // c half-width kept in regs
    constexpr int NH = CIN / CH;
    constexpr int WBUF = (PRELOAD ? KPB : 1) * CIN * DCHUNK;

    __shared__ int sh_idx[ROWS * KPB];
    __shared__ __align__(16) float sh_w[WBUF];
    __shared__ float sh_s[CIN];
    __shared__ float sh_t[CIN];

    const int tid = threadIdx.x;
    const int n0 = blockIdx.x * ROWS;
    const int dbase = blockIdx.y * DCHUNK;
    const int k0 = blockIdx.z * KPB;
    const int n = n0 + tid;

    // stage neighbor indices for this block's rows / k-range (coalesced-ish)
    #pragma unroll 1
    for (int i = tid; i < ROWS * KPB; i += ROWS) {
        int r = i / KPB, kk = i % KPB;
        sh_idx[i] = neigh[(size_t)(n0 + r) * K + (k0 + kk)];
    }
    if (NORM_IN) {
        for (int i = tid; i < CIN; i += ROWS) {
            sh_s[i] = sb[i];
            sh_t[i] = sb[CIN + i];
        }
    }
    if (PRELOAD) {
        #pragma unroll 1
        for (int i = tid; i < WBUF; i += ROWS) {
            int kk = i / (CIN * DCHUNK);
            int rem = i % (CIN * DCHUNK);
            int c = rem / DCHUNK, d = rem % DCHUNK;
            sh_w[i] = W[((size_t)(k0 + kk) * CIN + c) * COUT + dbase + d];
        }
    }
    __syncthreads();

    u64 acc[DCHUNK / 2];
    #pragma unroll
    for (int j = 0; j < DCHUNK / 2; ++j) acc[j] = 0ull;

    #pragma unroll 1
    for (int kk = 0; kk < KPB; ++kk) {
        if (!PRELOAD) {
            __syncthreads();
            #pragma unroll 1
            for (int i = tid; i < CIN * DCHUNK; i += ROWS) {
                int c = i / DCHUNK, d = i % DCHUNK;
                sh_w[i] = W[((size_t)(k0 + kk) * CIN + c) * COUT + dbase + d];
            }
            __syncthreads();
        }
        const float* wk = PRELOAD ? (sh_w + kk * CIN * DCHUNK) : sh_w;
        const int idx = sh_idx[tid * KPB + kk];
        const float* xrow = x + (size_t)idx * CIN;

        #pragma unroll
        for (int h = 0; h < NH; ++h) {
            float xh[CH];
            if (CH % 4 == 0) {
                #pragma unroll
                for (int j4 = 0; j4 < CH / 4; ++j4) {
                    float4 v = *(const float4*)(xrow + h * CH + j4 * 4);
                    xh[4 * j4 + 0] = v.x;
                    xh[4 * j4 + 1] = v.y;
                    xh[4 * j4 + 2] = v.z;
                    xh[4 * j4 + 3] = v.w;
                }
            } else {
                #pragma unroll
                for (int j = 0; j < CH; ++j) xh[j] = xrow[h * CH + j];
            }
            if (NORM_IN) {
                #pragma unroll
                for (int j = 0; j < CH; ++j)
                    xh[j] = fmaxf(xh[j] * sh_s[h * CH + j] + sh_t[h * CH + j], 0.f);
            }
            #pragma unroll
            for (int c = 0; c < CH; ++c) {
                u64 xv2 = pack2(xh[c]);
                const u64* wrow = (const u64*)(wk + (h * CH + c) * DCHUNK);
                #pragma unroll
                for (int j = 0; j < DCHUNK / 2; ++j) fma2(acc[j], xv2, wrow[j]);
            }
        }
    }

    float* yrow = y + (size_t)n * COUT + dbase;
    if (ACCUM) {
        #pragma unroll
        for (int j = 0; j < DCHUNK / 2; ++j) {
            float lo, hi;
            unpack2(acc[j], lo, hi);
            atomicAdd(yrow + 2 * j, lo);
            atomicAdd(yrow + 2 * j + 1, hi);
        }
    } else {
        #pragma unroll
        for (int j = 0; j < DCHUNK / 4; ++j) {
            float4 v;
            unpack2(acc[2 * j],     v.x, v.y);
            unpack2(acc[2 * j + 1], v.z, v.w);
            *(float4*)(yrow + 4 * j) = v;
        }
    }
}

// ---------------------------------------------------------------------------
// Per-channel sum / sumsq reduction. blockDim = (C, 8).
// ---------------------------------------------------------------------------
template <int C>
__global__ void stats_kernel(const float* __restrict__ y, int N,
                             float* __restrict__ stats)
{
    const int c = threadIdx.x;
    const int ty = threadIdx.y;
    float s = 0.f, q = 0.f;
    for (int r = blockIdx.x * blockDim.y + ty; r < N; r += gridDim.x * blockDim.y) {
        float v = y[(size_t)r * C + c];
        s += v;
        q += v * v;
    }
    __shared__ float sh[2][8][C];
    sh[0][ty][c] = s;
    sh[1][ty][c] = q;
    __syncthreads();
    if (ty == 0) {
        #pragma unroll
        for (int j = 1; j < 8; ++j) { s += sh[0][j][c]; q += sh[1][j][c]; }
        atomicAdd(&stats[c], s);
        atomicAdd(&stats[C + c], q);
    }
}

// ---------------------------------------------------------------------------
// BN finalize: scale/shift from batch stats. One block, C threads.
// ---------------------------------------------------------------------------
template <int C>
__global__ void finalize_kernel(const float* __restrict__ stats,
                                const float* __restrict__ g,
                                const float* __restrict__ b,
                                float* __restrict__ sb, float invN)
{
    int c = threadIdx.x;
    float mu = stats[c] * invN;
    float var = fmaxf(stats[C + c] * invN - mu * mu, 0.f);
    float s = g[c] * rsqrtf(var + BN_EPS);
    sb[c] = s;
    sb[C + c] = b[c] - mu * s;
}

// ---------------------------------------------------------------------------
// Final normalize + ReLU (in place on d_out)
// ---------------------------------------------------------------------------
__global__ void norm_out_kernel(float* __restrict__ out, const float* __restrict__ sb) {
    int i = blockIdx.x * blockDim.x + threadIdx.x;
    if (i < N2 * C2) {
        int c = i % C2;
        out[i] = fmaxf(out[i] * sb[c] + sb[C2 + c], 0.f);
    }
}

// ---------------------------------------------------------------------------
// Host launcher (graph-capturable: kernel launches only)
// ---------------------------------------------------------------------------
extern "C" void kernel_launch(void* const* d_in, const int* in_sizes, int n_in,
                              void* d_out, int out_size)
{
    const float* data   = (const float*)d_in[0];
    const int*   neigh0 = (const int*)  d_in[1];
    const int*   child0 = (const int*)  d_in[2];
    const int*   neigh1 = (const int*)  d_in[3];
    const int*   child1 = (const int*)  d_in[4];
    const int*   neigh2 = (const int*)  d_in[5];
    const float* w0  = (const float*)d_in[6];
    const float* g0  = (const float*)d_in[7];
    const float* b0  = (const float*)d_in[8];
    const float* wd0 = (const float*)d_in[9];
    const float* gd0 = (const float*)d_in[10];
    const float* bd0 = (const float*)d_in[11];
    const float* w1  = (const float*)d_in[12];
    const float* g1  = (const float*)d_in[13];
    const float* b1  = (const float*)d_in[14];
    const float* wd1 = (const float*)d_in[15];
    const float* gd1 = (const float*)d_in[16];
    const float* bd1 = (const float*)d_in[17];
    const float* wp  = (const float*)d_in[18];
    const float* gp  = (const float*)d_in[19];
    const float* bp  = (const float*)d_in[20];
    float* out = (float*)d_out;

    float *y0p, *y1p, *y2p, *y3p, *stp, *sbp;
    cudaGetSymbolAddress((void**)&y0p, g_y0);
    cudaGetSymbolAddress((void**)&y1p, g_y1);
    cudaGetSymbolAddress((void**)&y2p, g_y2);
    cudaGetSymbolAddress((void**)&y3p, g_y3);
    cudaGetSymbolAddress((void**)&stp, g_stats);
    cudaGetSymbolAddress((void**)&sbp, g_sb);

    init_kernel<<<512, 256>>>(out);

    // Stage A: data[N0,3] -> y0[N0,24]   (K=27, preload full W, direct store)
    conv_kernel<K3, K3, C_IN, C0, C0, false, true, false>
        <<<dim3(N0 / 256, 1, 1), 256>>>(data, neigh0, w0, nullptr, y0p, N0);
    stats_kernel<C0><<<256, dim3(C0, 8)>>>(y0p, N0, stp + 0);
    finalize_kernel<C0><<<1, C0>>>(stp + 0, g0, b0, sbp + 0, 1.f / N0);

    // Stage B: y0 -> y1[N1,48]   (K=8, split k into 2 groups of 4, atomic accum)
    conv_kernel<K2, 4, C0, C1, C1, true, true, true>
        <<<dim3(N1 / 256, 1, 2), 256>>>(y0p, child0, wd0, sbp + 0, y1p, N1);
    stats_kernel<C1><<<256, dim3(C1, 8)>>>(y1p, N1, stp + 192);
    finalize_kernel<C1><<<1, C1>>>(stp + 192, gd0, bd0, sbp + 192, 1.f / N1);

    // Stage C: y1 -> y2[N1,48]   (K=27, split k into 3 groups of 9, per-k W staging)
    conv_kernel<K3, 9, C1, C1, C1, true, false, true>
        <<<dim3(N1 / 256, 1, 3), 256>>>(y1p, neigh1, w1, sbp + 192, y2p, N1);
    stats_kernel<C1><<<256, dim3(C1, 8)>>>(y2p, N1, stp + 384);
    finalize_kernel<C1><<<1, C1>>>(stp + 384, g1, b1, sbp + 384, 1.f / N1);

    // Stage D: y2 -> y3[N2,96]   (K=8, 2 d-chunks, k split into 8 singles)
    conv_kernel<K2, 1, C1, C2, 48, true, true, true>
        <<<dim3(N2 / 256, 2, 8), 256>>>(y2p, child1, wd1, sbp + 384, y3p, N2);
    stats_kernel<C2><<<256, dim3(C2, 8)>>>(y3p, N2, stp + 576);
    finalize_kernel<C2><<<1, C2>>>(stp + 576, gd1, bd1, sbp + 576, 1.f / N2);

    // Stage E: y3 -> d_out[N2,96] raw conv  (K=27, 2 d-chunks, k split 9x3)
    conv_kernel<K3, 3, C2, C2, 48, true, false, true>
        <<<dim3(N2 / 256, 2, 9), 256>>>(y3p, neigh2, wp, sbp + 576, out, N2);
    stats_kernel<C2><<<256, dim3(C2, 8)>>>(out, N2, stp + 768);
    finalize_kernel<C2><<<1, C2>>>(stp + 768, gp, bp, sbp + 768, 1.f / N2);

    // Final BN + ReLU in place on d_out
    norm_out_kernel<<<(N2 * C2 + 255) / 256, 256>>>(out, sbp + 768);
}

// round 3
// speedup vs baseline: 1.1200x; 1.1183x over previous
#include <cuda_runtime.h>

#define N0 262144
#define N1 32768
#define N2 4096
#define BN_EPS 1e-5f

typedef unsigned long long u64;
typedef unsigned int u32;

__device__ __forceinline__ u64 pack2(float v) {
    u64 r; asm("mov.b64 %0, {%1, %1};" : "=l"(r) : "f"(v)); return r;
}
__device__ __forceinline__ void fma2(u64& d, u64 a, u64 b) {
    asm("fma.rn.f32x2 %0, %1, %2, %0;" : "+l"(d) : "l"(a), "l"(b));
}
__device__ __forceinline__ void unpack2(u64 v, float& lo, float& hi) {
    asm("mov.b64 {%0, %1}, %2;" : "=f"(lo), "=f"(hi) : "l"(v));
}
__device__ __forceinline__ void cp16(void* smem, const void* gmem) {
    u32 sa = (u32)__cvta_generic_to_shared(smem);
    asm volatile("cp.async.cg.shared.global [%0], [%1], 16;" :: "r"(sa), "l"(gmem));
}
__device__ __forceinline__ void cp_commit() { asm volatile("cp.async.commit_group;"); }
template <int W_> __device__ __forceinline__ void cp_wait() {
    asm volatile("cp.async.wait_group %0;" :: "n"(W_));
}

// ---------------- static scratch ----------------
__device__ float4 g_x4[N0];             // padded input rows
__device__ float g_y0[N0 * 24];
__device__ float g_y1[N1 * 48];
__device__ float g_y2[N1 * 48];
__device__ float g_y3[N2 * 96];
__device__ float g_pB[2 * N1 * 48];
__device__ float g_pC[3 * N1 * 48];
__device__ float g_pD[8 * N2 * 96];
__device__ float g_pE[9 * (size_t)N2 * 96];
__device__ float g_stats[5 * 192];      // per stage [sum|sumsq]
__device__ float g_sb[5 * 192];         // per stage [scale|shift]
__device__ u32   g_ctr[8];

__global__ void init_kernel() {
    int t = threadIdx.x;
    for (int i = t; i < 5 * 192; i += 256) g_stats[i] = 0.f;
    if (t < 8) g_ctr[t] = 0u;
}

__global__ void pad_kernel(const float* __restrict__ d) {
    int i = blockIdx.x * 256 + threadIdx.x;
    if (i < N0) {
        float4 v;
        v.x = d[3 * i]; v.y = d[3 * i + 1]; v.z = d[3 * i + 2]; v.w = 0.f;
        g_x4[i] = v;
    }
}

// ---------------------------------------------------------------------------
// Fused gather + input-BN/ReLU + conv contraction.
// Block: 256 threads, each owns R consecutive rows, DCHUNK output channels.
// W slice in smem (preload all KPB, or cp.async double-buffered per k).
// Writes partial slice z=blockIdx.z of y.
// ---------------------------------------------------------------------------
template <int K, int KPB, int CIN, int XSTRIDE, int COUT, int DCHUNK, int R,
          int CH, bool NORM_IN, bool DBLBUF>
__global__ void __launch_bounds__(256) conv_kernel(
    const float* __restrict__ x, const int* __restrict__ neigh,
    const float* __restrict__ W, const float* __restrict__ sb,
    float* __restrict__ y, int N)
{
    constexpr int WK = CIN * DCHUNK;
    constexpr int WSZ = DBLBUF ? 2 * WK : KPB * WK;
    __shared__ __align__(16) float sh_w[WSZ];
    __shared__ float sh_s[NORM_IN ? 2 * CIN : 2];

    const int tid = threadIdx.x;
    const int n0 = blockIdx.x * (256 * R);
    const int dbase = blockIdx.y * DCHUNK;
    const int k0 = blockIdx.z * KPB;
    const int n = n0 + tid * R;

    auto stageW = [&](int kk, int slot) {
        const float* src = W + (size_t)(k0 + kk) * CIN * COUT + dbase;
        float* dst = sh_w + slot * WK;
        #pragma unroll 1
        for (int i = tid; i < WK / 4; i += 256) {
            int c = i / (DCHUNK / 4), d4 = i % (DCHUNK / 4);
            cp16(dst + c * DCHUNK + d4 * 4, src + (size_t)c * COUT + d4 * 4);
        }
    };

    if (NORM_IN)
        for (int i = tid; i < 2 * CIN; i += 256) sh_s[i] = sb[i];

    if (DBLBUF) {
        stageW(0, 0); cp_commit();
    } else {
        #pragma unroll 1
        for (int kk = 0; kk < KPB; ++kk) stageW(kk, kk);
        cp_commit(); cp_wait<0>(); __syncthreads();
    }

    u64 acc[R][DCHUNK / 2] = {};

    #pragma unroll 1
    for (int kk = 0; kk < KPB; ++kk) {
        const float* wk;
        if (DBLBUF) {
            if (kk > 0) __syncthreads();
            if (kk + 1 < KPB) { stageW(kk + 1, (kk + 1) & 1); cp_commit(); cp_wait<1>(); }
            else cp_wait<0>();
            __syncthreads();
            wk = sh_w + (kk & 1) * WK;
        } else {
            wk = sh_w + kk * WK;
        }

        int idx[R];
        #pragma unroll
        for (int r = 0; r < R; ++r) idx[r] = neigh[(size_t)(n + r) * K + k0 + kk];

        #pragma unroll 1
        for (int h = 0; h < CIN / CH; ++h) {
            float xh[R][CH];
            #pragma unroll
            for (int r = 0; r < R; ++r) {
                const float* xr = x + (size_t)idx[r] * XSTRIDE + h * CH;
                if (CH == 3) {
                    float4 v = *(const float4*)xr;
                    xh[r][0] = v.x; xh[r][1] = v.y; xh[r][2] = v.z;
                } else {
                    #pragma unroll
                    for (int q = 0; q < CH / 4; ++q) {
                        float4 v = *(const float4*)(xr + 4 * q);
                        xh[r][4 * q + 0] = v.x; xh[r][4 * q + 1] = v.y;
                        xh[r][4 * q + 2] = v.z; xh[r][4 * q + 3] = v.w;
                    }
                }
                if (NORM_IN) {
                    #pragma unroll
                    for (int j = 0; j < CH; ++j)
                        xh[r][j] = fmaxf(xh[r][j] * sh_s[h * CH + j] + sh_s[CIN + h * CH + j], 0.f);
                }
            }
            #pragma unroll
            for (int c = 0; c < CH; ++c) {
                u64 xv[R];
                #pragma unroll
                for (int r = 0; r < R; ++r) xv[r] = pack2(xh[r][c]);
                const ulonglong2* wr = (const ulonglong2*)(wk + (h * CH + c) * DCHUNK);
                #pragma unroll
                for (int j = 0; j < DCHUNK / 4; ++j) {
                    ulonglong2 wv = wr[j];
                    #pragma unroll
                    for (int r = 0; r < R; ++r) {
                        fma2(acc[r][2 * j],     xv[r], wv.x);
                        fma2(acc[r][2 * j + 1], xv[r], wv.y);
                    }
                }
            }
        }
    }

    #pragma unroll
    for (int r = 0; r < R; ++r) {
        float* yr = y + ((size_t)blockIdx.z * N + (n + r)) * COUT + dbase;
        #pragma unroll
        for (int j = 0; j < DCHUNK / 4; ++j) {
            float4 v;
            unpack2(acc[r][2 * j],     v.x, v.y);
            unpack2(acc[r][2 * j + 1], v.z, v.w);
            *(float4*)(yr + 4 * j) = v;
        }
    }
}

// ---------------------------------------------------------------------------
// Combine KZ partials -> y, accumulate batch stats, last block finalizes BN
// scale/shift into sbout. blockDim = (C, TB).
// ---------------------------------------------------------------------------
template <int C, int KZ, int TB, bool WRITE_Y>
__global__ void combine_kernel(const float* __restrict__ p, float* __restrict__ y,
    int N, float* __restrict__ stats, const float* __restrict__ g,
    const float* __restrict__ b, float* __restrict__ sbout,
    u32* __restrict__ ctr, float invN)
{
    const int c = threadIdx.x, ty = threadIdx.y;
    float s = 0.f, q = 0.f;
    for (int r = blockIdx.x * TB + ty; r < N; r += gridDim.x * TB) {
        float v = 0.f;
        #pragma unroll
        for (int z = 0; z < KZ; ++z) v += p[((size_t)z * N + r) * C + c];
        if (WRITE_Y) y[(size_t)r * C + c] = v;
        s += v; q += v * v;
    }
    __shared__ float sh[2][TB][C];
    __shared__ bool last;
    sh[0][ty][c] = s; sh[1][ty][c] = q;
    __syncthreads();
    if (ty == 0) {
        #pragma unroll
        for (int j = 1; j < TB; ++j) { s += sh[0][j][c]; q += sh[1][j][c]; }
        atomicAdd(&stats[c], s);
        atomicAdd(&stats[C + c], q);
        __threadfence();
    }
    __syncthreads();
    if (ty == 0 && c == 0) {
        u32 old = atomicAdd(ctr, 1u);
        last = (old == gridDim.x - 1);
    }
    __syncthreads();
    if (last && ty == 0) {
        float mu = stats[c] * invN;
        float var = fmaxf(stats[C + c] * invN - mu * mu, 0.f);
        float sc = g[c] * rsqrtf(var + BN_EPS);
        sbout[c] = sc;
        sbout[C + c] = b[c] - mu * sc;
    }
}

__global__ void norm_out_kernel(float* __restrict__ out, const float* __restrict__ sb) {
    int i = blockIdx.x * 256 + threadIdx.x;
    if (i < N2 * 96) {
        int c = i % 96;
        out[i] = fmaxf(out[i] * sb[c] + sb[96 + c], 0.f);
    }
}

// ---------------------------------------------------------------------------
extern "C" void kernel_launch(void* const* d_in, const int* in_sizes, int n_in,
                              void* d_out, int out_size)
{
    const float* data   = (const float*)d_in[0];
    const int* neigh0 = (const int*)d_in[1];
    const int* child0 = (const int*)d_in[2];
    const int* neigh1 = (const int*)d_in[3];
    const int* child1 = (const int*)d_in[4];
    const int* neigh2 = (const int*)d_in[5];
    const float* w0 = (const float*)d_in[6];
    const float* g0 = (const float*)d_in[7];
    const float* b0 = (const float*)d_in[8];
    const float* wd0 = (const float*)d_in[9];
    const float* gd0 = (const float*)d_in[10];
    const float* bd0 = (const float*)d_in[11];
    const float* w1 = (const float*)d_in[12];
    const float* g1 = (const float*)d_in[13];
    const float* b1 = (const float*)d_in[14];
    const float* wd1 = (const float*)d_in[15];
    const float* gd1 = (const float*)d_in[16];
    const float* bd1 = (const float*)d_in[17];
    const float* wp = (const float*)d_in[18];
    const float* gp = (const float*)d_in[19];
    const float* bp = (const float*)d_in[20];
    float* out = (float*)d_out;

    float *x4p, *y0p, *y1p, *y2p, *y3p, *pBp, *pCp, *pDp, *pEp, *stp, *sbp;
    u32* ctrp;
    cudaGetSymbolAddress((void**)&x4p, g_x4);
    cudaGetSymbolAddress((void**)&y0p, g_y0);
    cudaGetSymbolAddress((void**)&y1p, g_y1);
    cudaGetSymbolAddress((void**)&y2p, g_y2);
    cudaGetSymbolAddress((void**)&y3p, g_y3);
    cudaGetSymbolAddress((void**)&pBp, g_pB);
    cudaGetSymbolAddress((void**)&pCp, g_pC);
    cudaGetSymbolAddress((void**)&pDp, g_pD);
    cudaGetSymbolAddress((void**)&pEp, g_pE);
    cudaGetSymbolAddress((void**)&stp, g_stats);
    cudaGetSymbolAddress((void**)&sbp, g_sb);
    cudaGetSymbolAddress((void**)&ctrp, g_ctr);

    init_kernel<<<1, 256>>>();
    pad_kernel<<<N0 / 256, 256>>>(data);

    // A: x4[N0,4(3)] -> y0[N0,24]; K=27 preload, R=2, direct store
    conv_kernel<27, 27, 3, 4, 24, 24, 2, 3, false, false>
        <<<dim3(512, 1, 1), 256>>>(x4p, neigh0, w0, nullptr, y0p, N0);
    combine_kernel<24, 1, 10, false><<<128, dim3(24, 10)>>>(
        y0p, nullptr, N0, stp + 0, g0, b0, sbp + 0, ctrp + 0, 1.f / N0);

    // B: y0 -> pB (kz=2, KPB=4 preload) -> y1[N1,48]
    conv_kernel<8, 4, 24, 24, 48, 48, 1, 8, true, false>
        <<<dim3(128, 1, 2), 256>>>(y0p, child0, wd0, sbp + 0, pBp, N1);
    combine_kernel<48, 2, 5, true><<<128, dim3(48, 5)>>>(
        pBp, y1p, N1, stp + 192, gd0, bd0, sbp + 192, ctrp + 1, 1.f / N1);

    // C: y1 -> pC (kz=3, KPB=9 dbl-buffered, R=2, d-split 2) -> y2[N1,48]
    conv_kernel<27, 9, 48, 48, 48, 24, 2, 8, true, true>
        <<<dim3(64, 2, 3), 256>>>(y1p, neigh1, w1, sbp + 192, pCp, N1);
    combine_kernel<48, 3, 5, true><<<128, dim3(48, 5)>>>(
        pCp, y2p, N1, stp + 384, g1, b1, sbp + 384, ctrp + 2, 1.f / N1);

    // D: y2 -> pD (kz=8, KPB=1 preload, d-split 2) -> y3[N2,96]
    conv_kernel<8, 1, 48, 48, 96, 48, 1, 8, true, false>
        <<<dim3(16, 2, 8), 256>>>(y2p, child1, wd1, sbp + 384, pDp, N2);
    combine_kernel<96, 8, 2, true><<<64, dim3(96, 2)>>>(
        pDp, y3p, N2, stp + 576, gd1, bd1, sbp + 576, ctrp + 3, 1.f / N2);

    // E: y3 -> pE (kz=9, KPB=3 dbl-buffered, d-split 2) -> out raw
    conv_kernel<27, 3, 96, 96, 96, 48, 1, 8, true, true>
        <<<dim3(16, 2, 9), 256>>>(y3p, neigh2, wp, sbp + 576, pEp, N2);
    combine_kernel<96, 9, 2, true><<<64, dim3(96, 2)>>>(
        pEp, out, N2, stp + 768, gp, bp, sbp + 768, ctrp + 4, 1.f / N2);

    // final BN + ReLU in place
    norm_out_kernel<<<(N2 * 96 + 255) / 256, 256>>>(out, sbp + 768);
}

// round 4
// speedup vs baseline: 1.2555x; 1.1210x over previous
#include <cuda_runtime.h>

#define N0 262144
#define N1 32768
#define N2 4096
#define BN_EPS 1e-5f

typedef unsigned long long u64;
typedef unsigned int u32;

__device__ __forceinline__ u64 pack2(float v) {
    u64 r; asm("mov.b64 %0, {%1, %1};" : "=l"(r) : "f"(v)); return r;
}
__device__ __forceinline__ void fma2(u64& d, u64 a, u64 b) {
    asm("fma.rn.f32x2 %0, %1, %2, %0;" : "+l"(d) : "l"(a), "l"(b));
}
__device__ __forceinline__ void unpack2(u64 v, float& lo, float& hi) {
    asm("mov.b64 {%0, %1}, %2;" : "=f"(lo), "=f"(hi) : "l"(v));
}
__device__ __forceinline__ void cp16(void* smem, const void* gmem) {
    u32 sa = (u32)__cvta_generic_to_shared(smem);
    asm volatile("cp.async.cg.shared.global [%0], [%1], 16;" :: "r"(sa), "l"(gmem));
}
__device__ __forceinline__ void cp_commit() { asm volatile("cp.async.commit_group;"); }
template <int W_> __device__ __forceinline__ void cp_wait() {
    asm volatile("cp.async.wait_group %0;" :: "n"(W_));
}

// ---------------- static scratch ----------------
__device__ float4 g_x4[N0];
__device__ float g_y0[N0 * 24];
__device__ float g_y1[N1 * 48];
__device__ float g_y2[N1 * 48];
__device__ float g_y3[N2 * 96];
__device__ float g_pB[2 * N1 * 48];
__device__ float g_pC[3 * N1 * 48];
__device__ float g_pD[8 * N2 * 96];
__device__ float g_pE[9 * (size_t)N2 * 96];
__device__ float g_stats[5 * 192];
__device__ float g_sb[5 * 192];
__device__ u32   g_ctr[8];

__global__ void init_kernel() {
    int t = threadIdx.x;
    for (int i = t; i < 5 * 192; i += 256) g_stats[i] = 0.f;
    if (t < 8) g_ctr[t] = 0u;
}

__global__ void pad_kernel(const float* __restrict__ d) {
    int i = blockIdx.x * 256 + threadIdx.x;
    if (i < N0) {
        float4 v;
        v.x = d[3 * i]; v.y = d[3 * i + 1]; v.z = d[3 * i + 2]; v.w = 0.f;
        g_x4[i] = v;
    }
}

// ---------------------------------------------------------------------------
// Fused gather + input-BN/ReLU + conv contraction (unchanged from R3).
// ---------------------------------------------------------------------------
template <int K, int KPB, int CIN, int XSTRIDE, int COUT, int DCHUNK, int R,
          int CH, bool NORM_IN, bool DBLBUF>
__global__ void __launch_bounds__(256) conv_kernel(
    const float* __restrict__ x, const int* __restrict__ neigh,
    const float* __restrict__ W, const float* __restrict__ sb,
    float* __restrict__ y, int N)
{
    constexpr int WK = CIN * DCHUNK;
    constexpr int WSZ = DBLBUF ? 2 * WK : KPB * WK;
    __shared__ __align__(16) float sh_w[WSZ];
    __shared__ float sh_s[NORM_IN ? 2 * CIN : 2];

    const int tid = threadIdx.x;
    const int n0 = blockIdx.x * (256 * R);
    const int dbase = blockIdx.y * DCHUNK;
    const int k0 = blockIdx.z * KPB;
    const int n = n0 + tid * R;

    auto stageW = [&](int kk, int slot) {
        const float* src = W + (size_t)(k0 + kk) * CIN * COUT + dbase;
        float* dst = sh_w + slot * WK;
        #pragma unroll 1
        for (int i = tid; i < WK / 4; i += 256) {
            int c = i / (DCHUNK / 4), d4 = i % (DCHUNK / 4);
            cp16(dst + c * DCHUNK + d4 * 4, src + (size_t)c * COUT + d4 * 4);
        }
    };

    if (NORM_IN)
        for (int i = tid; i < 2 * CIN; i += 256) sh_s[i] = sb[i];

    if (DBLBUF) {
        stageW(0, 0); cp_commit();
    } else {
        #pragma unroll 1
        for (int kk = 0; kk < KPB; ++kk) stageW(kk, kk);
        cp_commit(); cp_wait<0>(); __syncthreads();
    }

    u64 acc[R][DCHUNK / 2] = {};

    #pragma unroll 1
    for (int kk = 0; kk < KPB; ++kk) {
        const float* wk;
        if (DBLBUF) {
            if (kk > 0) __syncthreads();
            if (kk + 1 < KPB) { stageW(kk + 1, (kk + 1) & 1); cp_commit(); cp_wait<1>(); }
            else cp_wait<0>();
            __syncthreads();
            wk = sh_w + (kk & 1) * WK;
        } else {
            wk = sh_w + kk * WK;
        }

        int idx[R];
        #pragma unroll
        for (int r = 0; r < R; ++r) idx[r] = neigh[(size_t)(n + r) * K + k0 + kk];

        #pragma unroll 1
        for (int h = 0; h < CIN / CH; ++h) {
            float xh[R][CH];
            #pragma unroll
            for (int r = 0; r < R; ++r) {
                const float* xr = x + (size_t)idx[r] * XSTRIDE + h * CH;
                if (CH == 3) {
                    float4 v = *(const float4*)xr;
                    xh[r][0] = v.x; xh[r][1] = v.y; xh[r][2] = v.z;
                } else {
                    #pragma unroll
                    for (int q = 0; q < CH / 4; ++q) {
                        float4 v = *(const float4*)(xr + 4 * q);
                        xh[r][4 * q + 0] = v.x; xh[r][4 * q + 1] = v.y;
                        xh[r][4 * q + 2] = v.z; xh[r][4 * q + 3] = v.w;
                    }
                }
                if (NORM_IN) {
                    #pragma unroll
                    for (int j = 0; j < CH; ++j)
                        xh[r][j] = fmaxf(xh[r][j] * sh_s[h * CH + j] + sh_s[CIN + h * CH + j], 0.f);
                }
            }
            #pragma unroll
            for (int c = 0; c < CH; ++c) {
                u64 xv[R];
                #pragma unroll
                for (int r = 0; r < R; ++r) xv[r] = pack2(xh[r][c]);
                const ulonglong2* wr = (const ulonglong2*)(wk + (h * CH + c) * DCHUNK);
                #pragma unroll
                for (int j = 0; j < DCHUNK / 4; ++j) {
                    ulonglong2 wv = wr[j];
                    #pragma unroll
                    for (int r = 0; r < R; ++r) {
                        fma2(acc[r][2 * j],     xv[r], wv.x);
                        fma2(acc[r][2 * j + 1], xv[r], wv.y);
                    }
                }
            }
        }
    }

    #pragma unroll
    for (int r = 0; r < R; ++r) {
        float* yr = y + ((size_t)blockIdx.z * N + (n + r)) * COUT + dbase;
        #pragma unroll
        for (int j = 0; j < DCHUNK / 4; ++j) {
            float4 v;
            unpack2(acc[r][2 * j],     v.x, v.y);
            unpack2(acc[r][2 * j + 1], v.z, v.w);
            *(float4*)(yr + 4 * j) = v;
        }
    }
}

// ---------------------------------------------------------------------------
// Bandwidth-oriented combine: merge KZ partials -> y (float4 lanes), batch
// stats via block smem reduction + per-block atomics; last block finalizes BN.
// blockDim = (C/4, TB).
// ---------------------------------------------------------------------------
template <int C, int KZ, int TB, bool WRITE_Y>
__global__ void __launch_bounds__(256) combine_kernel(
    const float* __restrict__ p, float* __restrict__ y, int N,
    float* __restrict__ stats, const float* __restrict__ g,
    const float* __restrict__ b, float* __restrict__ sbout,
    u32* __restrict__ ctr, float invN)
{
    constexpr int V4 = C / 4;
    const int c4 = threadIdx.x;
    const int ty = threadIdx.y;

    float4 s = make_float4(0.f, 0.f, 0.f, 0.f);
    float4 q = make_float4(0.f, 0.f, 0.f, 0.f);

    #pragma unroll 2
    for (int r = blockIdx.x * TB + ty; r < N; r += gridDim.x * TB) {
        float4 v = *(const float4*)(p + (size_t)r * C + 4 * c4);
        #pragma unroll
        for (int z = 1; z < KZ; ++z) {
            float4 t = *(const float4*)(p + ((size_t)z * N + r) * C + 4 * c4);
            v.x += t.x; v.y += t.y; v.z += t.z; v.w += t.w;
        }
        if (WRITE_Y) *(float4*)(y + (size_t)r * C + 4 * c4) = v;
        s.x += v.x; s.y += v.y; s.z += v.z; s.w += v.w;
        q.x += v.x * v.x; q.y += v.y * v.y; q.z += v.z * v.z; q.w += v.w * v.w;
    }

    __shared__ float4 shs[TB][V4];
    __shared__ float4 shq[TB][V4];
    __shared__ bool last;
    shs[ty][c4] = s; shq[ty][c4] = q;
    __syncthreads();

    if (ty == 0) {
        #pragma unroll 4
        for (int j = 1; j < TB; ++j) {
            float4 a = shs[j][c4], d = shq[j][c4];
            s.x += a.x; s.y += a.y; s.z += a.z; s.w += a.w;
            q.x += d.x; q.y += d.y; q.z += d.z; q.w += d.w;
        }
        atomicAdd(&stats[4 * c4 + 0], s.x);
        atomicAdd(&stats[4 * c4 + 1], s.y);
        atomicAdd(&stats[4 * c4 + 2], s.z);
        atomicAdd(&stats[4 * c4 + 3], s.w);
        atomicAdd(&stats[C + 4 * c4 + 0], q.x);
        atomicAdd(&stats[C + 4 * c4 + 1], q.y);
        atomicAdd(&stats[C + 4 * c4 + 2], q.z);
        atomicAdd(&stats[C + 4 * c4 + 3], q.w);
        __threadfence();
    }
    __syncthreads();
    if (ty == 0 && c4 == 0)
        last = (atomicAdd(ctr, 1u) == gridDim.x - 1);
    __syncthreads();
    if (last && ty == 0) {
        __threadfence();
        #pragma unroll
        for (int j = 0; j < 4; ++j) {
            int c = 4 * c4 + j;
            float mu = stats[c] * invN;
            float var = fmaxf(stats[C + c] * invN - mu * mu, 0.f);
            float sc = g[c] * rsqrtf(var + BN_EPS);
            sbout[c] = sc;
            sbout[C + c] = b[c] - mu * sc;
        }
    }
}

__global__ void norm_out_kernel(float* __restrict__ out, const float* __restrict__ sb) {
    int i = blockIdx.x * 256 + threadIdx.x;
    if (i < N2 * 96) {
        int c = i % 96;
        out[i] = fmaxf(out[i] * sb[c] + sb[96 + c], 0.f);
    }
}

// ---------------------------------------------------------------------------
extern "C" void kernel_launch(void* const* d_in, const int* in_sizes, int n_in,
                              void* d_out, int out_size)
{
    const float* data   = (const float*)d_in[0];
    const int* neigh0 = (const int*)d_in[1];
    const int* child0 = (const int*)d_in[2];
    const int* neigh1 = (const int*)d_in[3];
    const int* child1 = (const int*)d_in[4];
    const int* neigh2 = (const int*)d_in[5];
    const float* w0 = (const float*)d_in[6];
    const float* g0 = (const float*)d_in[7];
    const float* b0 = (const float*)d_in[8];
    const float* wd0 = (const float*)d_in[9];
    const float* gd0 = (const float*)d_in[10];
    const float* bd0 = (const float*)d_in[11];
    const float* w1 = (const float*)d_in[12];
    const float* g1 = (const float*)d_in[13];
    const float* b1 = (const float*)d_in[14];
    const float* wd1 = (const float*)d_in[15];
    const float* gd1 = (const float*)d_in[16];
    const float* bd1 = (const float*)d_in[17];
    const float* wp = (const float*)d_in[18];
    const float* gp = (const float*)d_in[19];
    const float* bp = (const float*)d_in[20];
    float* out = (float*)d_out;

    float *x4p, *y0p, *y1p, *y2p, *y3p, *pBp, *pCp, *pDp, *pEp, *stp, *sbp;
    u32* ctrp;
    cudaGetSymbolAddress((void**)&x4p, g_x4);
    cudaGetSymbolAddress((void**)&y0p, g_y0);
    cudaGetSymbolAddress((void**)&y1p, g_y1);
    cudaGetSymbolAddress((void**)&y2p, g_y2);
    cudaGetSymbolAddress((void**)&y3p, g_y3);
    cudaGetSymbolAddress((void**)&pBp, g_pB);
    cudaGetSymbolAddress((void**)&pCp, g_pC);
    cudaGetSymbolAddress((void**)&pDp, g_pD);
    cudaGetSymbolAddress((void**)&pEp, g_pE);
    cudaGetSymbolAddress((void**)&stp, g_stats);
    cudaGetSymbolAddress((void**)&sbp, g_sb);
    cudaGetSymbolAddress((void**)&ctrp, g_ctr);

    init_kernel<<<1, 256>>>();
    pad_kernel<<<N0 / 256, 256>>>(data);

    // A: x4 -> y0[N0,24]
    conv_kernel<27, 27, 3, 4, 24, 24, 2, 3, false, false>
        <<<dim3(512, 1, 1), 256>>>(x4p, neigh0, w0, nullptr, y0p, N0);
    combine_kernel<24, 1, 42, false><<<1024, dim3(6, 42)>>>(
        y0p, nullptr, N0, stp + 0, g0, b0, sbp + 0, ctrp + 0, 1.f / N0);

    // B: y0 -> pB (kz=2) -> y1[N1,48]
    conv_kernel<8, 4, 24, 24, 48, 48, 1, 8, true, false>
        <<<dim3(128, 1, 2), 256>>>(y0p, child0, wd0, sbp + 0, pBp, N1);
    combine_kernel<48, 2, 21, true><<<512, dim3(12, 21)>>>(
        pBp, y1p, N1, stp + 192, gd0, bd0, sbp + 192, ctrp + 1, 1.f / N1);

    // C: y1 -> pC (kz=3, dbl-buffered, R=2, d-split 2) -> y2[N1,48]
    conv_kernel<27, 9, 48, 48, 48, 24, 2, 8, true, true>
        <<<dim3(64, 2, 3), 256>>>(y1p, neigh1, w1, sbp + 192, pCp, N1);
    combine_kernel<48, 3, 21, true><<<512, dim3(12, 21)>>>(
        pCp, y2p, N1, stp + 384, g1, b1, sbp + 384, ctrp + 2, 1.f / N1);

    // D: y2 -> pD (kz=8, d-split 2) -> y3[N2,96]
    conv_kernel<8, 1, 48, 48, 96, 48, 1, 8, true, false>
        <<<dim3(16, 2, 8), 256>>>(y2p, child1, wd1, sbp + 384, pDp, N2);
    combine_kernel<96, 8, 10, true><<<256, dim3(24, 10)>>>(
        pDp, y3p, N2, stp + 576, gd1, bd1, sbp + 576, ctrp + 3, 1.f / N2);

    // E: y3 -> pE (kz=9, dbl-buffered, d-split 2) -> out raw
    conv_kernel<27, 3, 96, 96, 96, 48, 1, 8, true, true>
        <<<dim3(16, 2, 9), 256>>>(y3p, neigh2, wp, sbp + 576, pEp, N2);
    combine_kernel<96, 9, 10, true><<<256, dim3(24, 10)>>>(
        pEp, out, N2, stp + 768, gp, bp, sbp + 768, ctrp + 4, 1.f / N2);

    norm_out_kernel<<<(N2 * 96 + 255) / 256, 256>>>(out, sbp + 768);
}